// round 1
// baseline (speedup 1.0000x reference)
#include <cuda_runtime.h>

// MMD loss reduced to closed form over column sums:
//   result = 7.75 * n(n-1) * ||colsum(s)-colsum(t)||^2
//            / ((n*(sum s^2 + sum t^2) - ||colsum(s)+colsum(t)||^2) * B^2)
// with n = 2B. The max-min scale cancels exactly, so no extrema pass needed.

#define NBLK 128
#define NTHR 256
#define DDIM 256
#define D4   64   // DDIM / 4

__device__ float g_cs[NBLK][DDIM];  // per-block colsum(source)
__device__ float g_ct[NBLK][DDIM];  // per-block colsum(target)
__device__ float g_sq[NBLK];        // per-block sum of squares (s + t combined)

__global__ __launch_bounds__(NTHR)
void mmd_partial(const float4* __restrict__ s4, const float4* __restrict__ t4, int B) {
    const int tid = threadIdx.x;
    const int c4  = tid & 63;   // which float4 column group (0..63)
    const int ro  = tid >> 6;   // row offset within 4-row tile (0..3)

    float4 as = make_float4(0.f, 0.f, 0.f, 0.f);
    float4 at = make_float4(0.f, 0.f, 0.f, 0.f);
    float  sq = 0.f;

    for (int r = blockIdx.x * 4 + ro; r < B; r += NBLK * 4) {
        float4 v = s4[(long)r * D4 + c4];
        as.x += v.x; as.y += v.y; as.z += v.z; as.w += v.w;
        sq += v.x * v.x + v.y * v.y + v.z * v.z + v.w * v.w;
        float4 w = t4[(long)r * D4 + c4];
        at.x += w.x; at.y += w.y; at.z += w.z; at.w += w.w;
        sq += w.x * w.x + w.y * w.y + w.z * w.z + w.w * w.w;
    }

    __shared__ float4 sm[NTHR];
    __shared__ float  smq[NTHR];

    sm[tid]  = as;
    smq[tid] = sq;
    __syncthreads();

    if (ro == 0) {
        float4 a = sm[c4], b = sm[64 + c4], c = sm[128 + c4], d = sm[192 + c4];
        float4 r4;
        r4.x = (a.x + b.x) + (c.x + d.x);
        r4.y = (a.y + b.y) + (c.y + d.y);
        r4.z = (a.z + b.z) + (c.z + d.z);
        r4.w = (a.w + b.w) + (c.w + d.w);
        reinterpret_cast<float4*>(g_cs[blockIdx.x])[c4] = r4;
    }
    __syncthreads();

    sm[tid] = at;
    __syncthreads();

    if (ro == 0) {
        float4 a = sm[c4], b = sm[64 + c4], c = sm[128 + c4], d = sm[192 + c4];
        float4 r4;
        r4.x = (a.x + b.x) + (c.x + d.x);
        r4.y = (a.y + b.y) + (c.y + d.y);
        r4.z = (a.z + b.z) + (c.z + d.z);
        r4.w = (a.w + b.w) + (c.w + d.w);
        reinterpret_cast<float4*>(g_ct[blockIdx.x])[c4] = r4;
    }

    // tree-reduce the sum of squares
    for (int s = NTHR / 2; s > 0; s >>= 1) {
        __syncthreads();
        if (tid < s) smq[tid] += smq[tid + s];
    }
    if (tid == 0) g_sq[blockIdx.x] = smq[0];
}

__global__ __launch_bounds__(NTHR)
void mmd_final(float* __restrict__ out, int B) {
    const int tid = threadIdx.x;

    // Per-column totals across the NBLK partials (float accumulation is
    // plenty: 128 partials, magnitudes O(100)).
    float cs = 0.f, ct = 0.f;
#pragma unroll 8
    for (int b = 0; b < NBLK; b++) {
        cs += g_cs[b][tid];
        ct += g_ct[b][tid];
    }

    double delta = (double)cs - (double)ct;
    double msum  = (double)cs + (double)ct;
    double d2 = delta * delta;
    double m2 = msum * msum;
    double sq = (tid < NBLK) ? (double)g_sq[tid] : 0.0;

    __shared__ double sd[NTHR], sm2[NTHR], ssq[NTHR];
    sd[tid]  = d2;
    sm2[tid] = m2;
    ssq[tid] = sq;
    for (int s = NTHR / 2; s > 0; s >>= 1) {
        __syncthreads();
        if (tid < s) {
            sd[tid]  += sd[tid + s];
            sm2[tid] += sm2[tid + s];
            ssq[tid] += ssq[tid + s];
        }
    }
    if (tid == 0) {
        double n  = 2.0 * (double)B;
        double Bd = (double)B;
        double Sp = ssq[0];
        double res = 7.75 * n * (n - 1.0) * sd[0] / ((n * Sp - sm2[0]) * Bd * Bd);
        out[0] = (float)res;
    }
}

extern "C" void kernel_launch(void* const* d_in, const int* in_sizes, int n_in,
                              void* d_out, int out_size) {
    const float* s = (const float*)d_in[0];
    const float* t = (const float*)d_in[1];
    int B = in_sizes[0] / DDIM;  // 4096 for this problem

    mmd_partial<<<NBLK, NTHR>>>((const float4*)s, (const float4*)t, B);
    mmd_final<<<1, NTHR>>>((float*)d_out, B);
}